// round 2
// baseline (speedup 1.0000x reference)
#include <cuda_runtime.h>
#include <math.h>

#define Nn 500000
#define Ee 16000000
#define Gg 5000
#define DIMc 10
#define STRIDEc 12
#define FINc 64
#define SCAN_B 1024
#define NB_SCAN ((Nn + SCAN_B - 1) / SCAN_B)   // 489

// ---------- static device scratch (no allocations allowed) ----------
__device__ __align__(16) float g_ya[(size_t)Nn * STRIDEc];
__device__ __align__(16) float g_yb[(size_t)Nn * STRIDEc];
__device__ int   g_deg[Nn];
__device__ int   g_rowptr[Nn + 1];
__device__ int   g_cursor[Nn];
__device__ int   g_csr[Ee];
__device__ int   g_bsums[SCAN_B];
__device__ float g_sacc[Gg];
__device__ float g_cnt[Gg];

// ---------- init: zero histogram + readout accumulators ----------
__global__ void k_init() {
    int i = blockIdx.x * blockDim.x + threadIdx.x;
    if (i < Nn) g_deg[i] = 0;
    if (i < Gg) { g_sacc[i] = 0.0f; g_cnt[i] = 0.0f; }
}

// ---------- degree histogram ----------
__global__ void k_hist(const int* __restrict__ dst) {
    int e = blockIdx.x * blockDim.x + threadIdx.x;
    if (e < Ee) atomicAdd(&g_deg[dst[e]], 1);
}

// ---------- exclusive scan (3 kernels) ----------
__global__ void k_scan1() {
    __shared__ int sh[SCAN_B];
    int gid = blockIdx.x * SCAN_B + threadIdx.x;
    int v = (gid < Nn) ? g_deg[gid] : 0;
    sh[threadIdx.x] = v;
    __syncthreads();
    #pragma unroll
    for (int off = 1; off < SCAN_B; off <<= 1) {
        int t = (threadIdx.x >= off) ? sh[threadIdx.x - off] : 0;
        __syncthreads();
        sh[threadIdx.x] += t;
        __syncthreads();
    }
    if (gid < Nn) g_rowptr[gid] = sh[threadIdx.x] - v;   // exclusive
    if (threadIdx.x == SCAN_B - 1) g_bsums[blockIdx.x] = sh[SCAN_B - 1];
}

__global__ void k_scan2(int nb) {
    __shared__ int sh[SCAN_B];
    int v = (threadIdx.x < nb) ? g_bsums[threadIdx.x] : 0;
    sh[threadIdx.x] = v;
    __syncthreads();
    #pragma unroll
    for (int off = 1; off < SCAN_B; off <<= 1) {
        int t = (threadIdx.x >= off) ? sh[threadIdx.x - off] : 0;
        __syncthreads();
        sh[threadIdx.x] += t;
        __syncthreads();
    }
    if (threadIdx.x < nb) g_bsums[threadIdx.x] = sh[threadIdx.x] - v; // exclusive
}

__global__ void k_scan3() {
    int gid = blockIdx.x * SCAN_B + threadIdx.x;
    if (gid < Nn) {
        int r = g_rowptr[gid] + g_bsums[blockIdx.x];
        g_rowptr[gid] = r;
        g_cursor[gid] = r;
    }
    if (gid == 0) g_rowptr[Nn] = Ee;
}

// ---------- scatter edges into CSR (by dst) ----------
__global__ void k_scatter(const int* __restrict__ src, const int* __restrict__ dst) {
    int e = blockIdx.x * blockDim.x + threadIdx.x;
    if (e < Ee) {
        int p = atomicAdd(&g_cursor[dst[e]], 1);
        g_csr[p] = src[e];
    }
}

// ---------- layer-1 projection: y1 = h @ W1_1  (64 -> 10), plus graph counts ----------
__global__ void k_proj1(const float* __restrict__ h, const float* __restrict__ W1,
                        const int* __restrict__ ng) {
    __shared__ float sW[FINc * DIMc];
    for (int t = threadIdx.x; t < FINc * DIMc; t += blockDim.x) sW[t] = W1[t];
    __syncthreads();
    int i = blockIdx.x * blockDim.x + threadIdx.x;
    if (i >= Nn) return;

    float acc[DIMc];
    #pragma unroll
    for (int j = 0; j < DIMc; j++) acc[j] = 0.0f;

    const float4* hp = reinterpret_cast<const float4*>(h + (size_t)i * FINc);
    #pragma unroll
    for (int c4 = 0; c4 < FINc / 4; c4++) {
        float4 hv = __ldg(&hp[c4]);
        int c = c4 * 4;
        #pragma unroll
        for (int j = 0; j < DIMc; j++) {
            acc[j] += hv.x * sW[(c + 0) * DIMc + j];
            acc[j] += hv.y * sW[(c + 1) * DIMc + j];
            acc[j] += hv.z * sW[(c + 2) * DIMc + j];
            acc[j] += hv.w * sW[(c + 3) * DIMc + j];
        }
    }
    float* o = g_ya + (size_t)i * STRIDEc;
    *reinterpret_cast<float4*>(o)     = make_float4(acc[0], acc[1], acc[2], acc[3]);
    *reinterpret_cast<float4*>(o + 4) = make_float4(acc[4], acc[5], acc[6], acc[7]);
    *reinterpret_cast<float2*>(o + 8) = make_float2(acc[8], acc[9]);

    atomicAdd(&g_cnt[ng[i]], 1.0f);
}

// ---------- fused layer: agg + MLP + readout + next-layer projection ----------
// PING==0: read g_ya, write g_yb. PING==1: read g_yb, write g_ya.
// Buffers are resolved in DEVICE code (passing __device__ symbols from host
// yields the host shadow address, which ATS silently maps on GB300).
template <int PING, bool LAST>
__global__ void k_layer(const float* __restrict__ b1, const float* __restrict__ W2,
                        const float* __restrict__ b2, const float* __restrict__ l,
                        const float* __restrict__ W1n, const int* __restrict__ ng) {
    const float* __restrict__ yin  = (PING == 0) ? g_ya : g_yb;
    float* __restrict__       yout = (PING == 0) ? g_yb : g_ya;

    __shared__ float sW2[DIMc * DIMc], sW1n[DIMc * DIMc], sb1[DIMc], sb2[DIMc], sl[DIMc];
    int t = threadIdx.x;
    if (t < DIMc * DIMc) {
        sW2[t] = W2[t];
        if (!LAST) sW1n[t] = W1n[t];
    }
    if (t < DIMc) { sb1[t] = b1[t]; sb2[t] = b2[t]; sl[t] = l[t]; }
    __syncthreads();

    int i = blockIdx.x * blockDim.x + t;
    if (i >= Nn) return;

    const float* yrow = yin + (size_t)i * STRIDEc;
    float4 a0 = *reinterpret_cast<const float4*>(yrow);
    float4 a1 = *reinterpret_cast<const float4*>(yrow + 4);
    float2 a2 = *reinterpret_cast<const float2*>(yrow + 8);

    int e = g_rowptr[i];
    int end = g_rowptr[i + 1];
    for (; e < end; e++) {
        int s = __ldg(&g_csr[e]);
        const float* p = yin + (size_t)s * STRIDEc;
        float4 f0 = __ldg(reinterpret_cast<const float4*>(p));
        float4 f1 = __ldg(reinterpret_cast<const float4*>(p + 4));
        float2 f2 = __ldg(reinterpret_cast<const float2*>(p + 8));
        a0.x += f0.x; a0.y += f0.y; a0.z += f0.z; a0.w += f0.w;
        a1.x += f1.x; a1.y += f1.y; a1.z += f1.z; a1.w += f1.w;
        a2.x += f2.x; a2.y += f2.y;
    }

    // u = relu(acc + b1)
    float u[DIMc];
    u[0] = fmaxf(a0.x + sb1[0], 0.0f);
    u[1] = fmaxf(a0.y + sb1[1], 0.0f);
    u[2] = fmaxf(a0.z + sb1[2], 0.0f);
    u[3] = fmaxf(a0.w + sb1[3], 0.0f);
    u[4] = fmaxf(a1.x + sb1[4], 0.0f);
    u[5] = fmaxf(a1.y + sb1[5], 0.0f);
    u[6] = fmaxf(a1.z + sb1[6], 0.0f);
    u[7] = fmaxf(a1.w + sb1[7], 0.0f);
    u[8] = fmaxf(a2.x + sb1[8], 0.0f);
    u[9] = fmaxf(a2.y + sb1[9], 0.0f);

    // x = relu(u @ W2 + b2)
    float x[DIMc];
    #pragma unroll
    for (int j = 0; j < DIMc; j++) {
        float tv = sb2[j];
        #pragma unroll
        for (int k = 0; k < DIMc; k++) tv += u[k] * sW2[k * DIMc + j];
        x[j] = fmaxf(tv, 0.0f);
    }

    // readout contribution: x . l
    float dot = 0.0f;
    #pragma unroll
    for (int j = 0; j < DIMc; j++) dot += x[j] * sl[j];
    atomicAdd(&g_sacc[ng[i]], dot);

    if (!LAST) {
        // y_next = x @ W1_next
        float yn[DIMc];
        #pragma unroll
        for (int j2 = 0; j2 < DIMc; j2++) {
            float v = 0.0f;
            #pragma unroll
            for (int j = 0; j < DIMc; j++) v += x[j] * sW1n[j * DIMc + j2];
            yn[j2] = v;
        }
        float* o = yout + (size_t)i * STRIDEc;
        *reinterpret_cast<float4*>(o)     = make_float4(yn[0], yn[1], yn[2], yn[3]);
        *reinterpret_cast<float4*>(o + 4) = make_float4(yn[4], yn[5], yn[6], yn[7]);
        *reinterpret_cast<float2*>(o + 8) = make_float2(yn[8], yn[9]);
    }
}

// ---------- final: out[g] = sigmoid(sacc[g] / max(cnt[g],1)) ----------
__global__ void k_final(float* __restrict__ out) {
    int g = blockIdx.x * blockDim.x + threadIdx.x;
    if (g < Gg) {
        float c = fmaxf(g_cnt[g], 1.0f);
        float s = g_sacc[g] / c;
        out[g] = 1.0f / (1.0f + expf(-s));
    }
}

extern "C" void kernel_launch(void* const* d_in, const int* in_sizes, int n_in,
                              void* d_out, int out_size) {
    const float* h   = (const float*)d_in[0];
    const int*   src = (const int*)d_in[1];
    const int*   dst = (const int*)d_in[2];
    const int*   ng  = (const int*)d_in[3];
    // per-layer params at 4 + 5*(i-1): W1, b1, W2, b2, l
    const float* W1[5]; const float* b1[5]; const float* W2[5];
    const float* b2[5]; const float* ll[5];
    for (int i = 0; i < 5; i++) {
        W1[i] = (const float*)d_in[4 + 5 * i + 0];
        b1[i] = (const float*)d_in[4 + 5 * i + 1];
        W2[i] = (const float*)d_in[4 + 5 * i + 2];
        b2[i] = (const float*)d_in[4 + 5 * i + 3];
        ll[i] = (const float*)d_in[4 + 5 * i + 4];
    }
    float* out = (float*)d_out;

    const int TB = 256;
    int nblk  = (Nn + TB - 1) / TB;
    int eblk  = (Ee + TB - 1) / TB;
    int gblk  = (Gg + TB - 1) / TB;

    k_init<<<nblk, TB>>>();
    k_hist<<<eblk, TB>>>(dst);
    k_scan1<<<NB_SCAN, SCAN_B>>>();
    k_scan2<<<1, SCAN_B>>>(NB_SCAN);
    k_scan3<<<NB_SCAN, SCAN_B>>>();
    k_scatter<<<eblk, TB>>>(src, dst);

    k_proj1<<<nblk, TB>>>(h, W1[0], ng);

    // ping-pong: ya -> yb -> ya -> yb -> ya
    k_layer<0, false><<<nblk, TB>>>(b1[0], W2[0], b2[0], ll[0], W1[1], ng);
    k_layer<1, false><<<nblk, TB>>>(b1[1], W2[1], b2[1], ll[1], W1[2], ng);
    k_layer<0, false><<<nblk, TB>>>(b1[2], W2[2], b2[2], ll[2], W1[3], ng);
    k_layer<1, false><<<nblk, TB>>>(b1[3], W2[3], b2[3], ll[3], W1[4], ng);
    k_layer<0, true ><<<nblk, TB>>>(b1[4], W2[4], b2[4], ll[4], nullptr, ng);

    k_final<<<gblk, TB>>>(out);
}

// round 3
// speedup vs baseline: 1.3037x; 1.3037x over previous
#include <cuda_runtime.h>
#include <cuda_fp16.h>
#include <math.h>

#define Nn 500000
#define Ee 16000000
#define Gg 5000
#define DIMc 10
#define FINc 64
#define SCAN_B 1024
#define NB_SCAN ((Nn + SCAN_B - 1) / SCAN_B)   // 489
#define CSRP (Ee + 8 * Nn)                      // padded CSR capacity (20M)
#define RSTRIDE 16                              // halves per row (32 bytes)

// ---------- static device scratch ----------
// Feature tables: Nn+1 rows of 16 halves; row Nn is the dummy zero row
// (BSS zero-init, never written).
__device__ __align__(16) __half g_ha[((size_t)Nn + 1) * RSTRIDE];
__device__ __align__(16) __half g_hb[((size_t)Nn + 1) * RSTRIDE];
__device__ int   g_deg[Nn];
__device__ int   g_rowptr[Nn];      // exclusive scan of padded degrees
__device__ int   g_cursor[Nn];
__device__ int   g_csr[CSRP];
__device__ int   g_bsums[SCAN_B];
__device__ float g_sacc[Gg];
__device__ float g_cnt[Gg];

// ---------- init ----------
__global__ void k_init() {
    int i = blockIdx.x * blockDim.x + threadIdx.x;
    if (i < Nn) g_deg[i] = 0;
    if (i < Gg) { g_sacc[i] = 0.0f; g_cnt[i] = 0.0f; }
}

// fill csr with dummy id (Nn) so padded slots aggregate the zero row
__global__ void k_fillcsr() {
    int i = blockIdx.x * blockDim.x + threadIdx.x;
    if (i < CSRP) g_csr[i] = Nn;
}

// ---------- degree histogram ----------
__global__ void k_hist(const int* __restrict__ dst) {
    int e = blockIdx.x * blockDim.x + threadIdx.x;
    if (e < Ee) atomicAdd(&g_deg[dst[e]], 1);
}

// ---------- exclusive scan of PADDED degrees ----------
__global__ void k_scan1() {
    __shared__ int sh[SCAN_B];
    int gid = blockIdx.x * SCAN_B + threadIdx.x;
    int v = 0;
    if (gid < Nn) v = (g_deg[gid] + 7) & ~7;
    sh[threadIdx.x] = v;
    __syncthreads();
    #pragma unroll
    for (int off = 1; off < SCAN_B; off <<= 1) {
        int t = (threadIdx.x >= off) ? sh[threadIdx.x - off] : 0;
        __syncthreads();
        sh[threadIdx.x] += t;
        __syncthreads();
    }
    if (gid < Nn) g_rowptr[gid] = sh[threadIdx.x] - v;
    if (threadIdx.x == SCAN_B - 1) g_bsums[blockIdx.x] = sh[SCAN_B - 1];
}

__global__ void k_scan2(int nb) {
    __shared__ int sh[SCAN_B];
    int v = (threadIdx.x < nb) ? g_bsums[threadIdx.x] : 0;
    sh[threadIdx.x] = v;
    __syncthreads();
    #pragma unroll
    for (int off = 1; off < SCAN_B; off <<= 1) {
        int t = (threadIdx.x >= off) ? sh[threadIdx.x - off] : 0;
        __syncthreads();
        sh[threadIdx.x] += t;
        __syncthreads();
    }
    if (threadIdx.x < nb) g_bsums[threadIdx.x] = sh[threadIdx.x] - v;
}

__global__ void k_scan3() {
    int gid = blockIdx.x * SCAN_B + threadIdx.x;
    if (gid < Nn) {
        int r = g_rowptr[gid] + g_bsums[blockIdx.x];
        g_rowptr[gid] = r;
        g_cursor[gid] = r;
    }
}

// ---------- scatter edges into CSR (by dst) ----------
__global__ void k_scatter(const int* __restrict__ src, const int* __restrict__ dst) {
    int e = blockIdx.x * blockDim.x + threadIdx.x;
    if (e < Ee) {
        int p = atomicAdd(&g_cursor[dst[e]], 1);
        g_csr[p] = src[e];
    }
}

// ---------- helpers ----------
__device__ __forceinline__ void add8(float* acc, uint4 v) {
    float2 f;
    f = __half22float2(*reinterpret_cast<__half2*>(&v.x)); acc[0] += f.x; acc[1] += f.y;
    f = __half22float2(*reinterpret_cast<__half2*>(&v.y)); acc[2] += f.x; acc[3] += f.y;
    f = __half22float2(*reinterpret_cast<__half2*>(&v.z)); acc[4] += f.x; acc[5] += f.y;
    f = __half22float2(*reinterpret_cast<__half2*>(&v.w)); acc[6] += f.x; acc[7] += f.y;
}

__device__ __forceinline__ void store_row10(__half* row, const float* y) {
    __half2 p0 = __floats2half2_rn(y[0], y[1]);
    __half2 p1 = __floats2half2_rn(y[2], y[3]);
    __half2 p2 = __floats2half2_rn(y[4], y[5]);
    __half2 p3 = __floats2half2_rn(y[6], y[7]);
    __half2 p4 = __floats2half2_rn(y[8], y[9]);
    uint4 o;
    o.x = *reinterpret_cast<unsigned*>(&p0);
    o.y = *reinterpret_cast<unsigned*>(&p1);
    o.z = *reinterpret_cast<unsigned*>(&p2);
    o.w = *reinterpret_cast<unsigned*>(&p3);
    *reinterpret_cast<uint4*>(row) = o;
    *reinterpret_cast<unsigned*>(row + 8) = *reinterpret_cast<unsigned*>(&p4);
}

// ---------- layer-1 projection: y1 = h @ W1_1 (64 -> 10), fp16 out, + counts ----------
__global__ void k_proj1(const float* __restrict__ h, const float* __restrict__ W1,
                        const int* __restrict__ ng) {
    __shared__ float sW[FINc * DIMc];
    for (int t = threadIdx.x; t < FINc * DIMc; t += blockDim.x) sW[t] = W1[t];
    __syncthreads();
    int i = blockIdx.x * blockDim.x + threadIdx.x;
    if (i >= Nn) return;

    float acc[DIMc];
    #pragma unroll
    for (int j = 0; j < DIMc; j++) acc[j] = 0.0f;

    const float4* hp = reinterpret_cast<const float4*>(h + (size_t)i * FINc);
    #pragma unroll
    for (int c4 = 0; c4 < FINc / 4; c4++) {
        float4 hv = __ldg(&hp[c4]);
        int c = c4 * 4;
        #pragma unroll
        for (int j = 0; j < DIMc; j++) {
            acc[j] += hv.x * sW[(c + 0) * DIMc + j];
            acc[j] += hv.y * sW[(c + 1) * DIMc + j];
            acc[j] += hv.z * sW[(c + 2) * DIMc + j];
            acc[j] += hv.w * sW[(c + 3) * DIMc + j];
        }
    }
    store_row10(g_ha + (size_t)i * RSTRIDE, acc);
    atomicAdd(&g_cnt[ng[i]], 1.0f);
}

// ---------- fused layer: pair-per-node gather + MLP + readout + next projection ----------
template <int PING, bool LAST>
__global__ void __launch_bounds__(256) k_layer(
        const float* __restrict__ b1, const float* __restrict__ W2,
        const float* __restrict__ b2, const float* __restrict__ l,
        const float* __restrict__ W1n, const int* __restrict__ ng) {
    const __half* __restrict__ yin = (PING == 0) ? g_ha : g_hb;
    __half* __restrict__       yout = (PING == 0) ? g_hb : g_ha;

    __shared__ float sW2[DIMc * DIMc], sW1n[DIMc * DIMc], sb1[DIMc], sb2[DIMc], sl[DIMc];
    int t = threadIdx.x;
    if (t < DIMc * DIMc) {
        sW2[t] = W2[t];
        if (!LAST) sW1n[t] = W1n[t];
    }
    if (t < DIMc) { sb1[t] = b1[t]; sb2[t] = b2[t]; sl[t] = l[t]; }
    __syncthreads();

    int lane = t & 31;
    int warp_global = (blockIdx.x * blockDim.x + t) >> 5;
    int sub = lane & 1;                 // which 16B half of the 32B row
    int i = warp_global * 16 + (lane >> 1);
    if (i >= Nn) return;                // warp-uniform (Nn % 16 == 0)

    int e0 = g_rowptr[i];
    int iters = (g_deg[i] + 7) >> 3;
    int itersW = __reduce_max_sync(0xffffffffu, iters);

    // self term
    float acc[8] = {0, 0, 0, 0, 0, 0, 0, 0};
    add8(acc, __ldg(reinterpret_cast<const uint4*>(yin + (size_t)i * RSTRIDE + sub * 8)));

    const int baselane = lane & ~1;
    for (int it = 0; it < itersW; ++it) {
        bool live = (it < iters);
        int idx = e0 + it * 8 + sub * 4;
        if (idx > CSRP - 4) idx = CSRP - 4;             // clamp (dead lanes only)
        int4 idv = *reinterpret_cast<const int4*>(g_csr + idx);
        int id[4] = {idv.x, idv.y, idv.z, idv.w};
        #pragma unroll
        for (int k = 0; k < 8; ++k) {
            int s = __shfl_sync(0xffffffffu, id[k & 3], baselane + (k >> 2));
            if (!live) s = Nn;                          // dummy zero row
            add8(acc, __ldg(reinterpret_cast<const uint4*>(
                    yin + (size_t)s * RSTRIDE + sub * 8)));
        }
    }

    // even lane collects values 8,9 from odd lane
    float v8 = __shfl_down_sync(0xffffffffu, acc[0], 1);
    float v9 = __shfl_down_sync(0xffffffffu, acc[1], 1);

    if (sub == 0) {
        float u[DIMc];
        #pragma unroll
        for (int j = 0; j < 8; j++) u[j] = fmaxf(acc[j] + sb1[j], 0.0f);
        u[8] = fmaxf(v8 + sb1[8], 0.0f);
        u[9] = fmaxf(v9 + sb1[9], 0.0f);

        float x[DIMc];
        #pragma unroll
        for (int j = 0; j < DIMc; j++) {
            float tv = sb2[j];
            #pragma unroll
            for (int k = 0; k < DIMc; k++) tv += u[k] * sW2[k * DIMc + j];
            x[j] = fmaxf(tv, 0.0f);
        }

        float dot = 0.0f;
        #pragma unroll
        for (int j = 0; j < DIMc; j++) dot += x[j] * sl[j];
        atomicAdd(&g_sacc[ng[i]], dot);

        if (!LAST) {
            float yn[DIMc];
            #pragma unroll
            for (int j2 = 0; j2 < DIMc; j2++) {
                float v = 0.0f;
                #pragma unroll
                for (int j = 0; j < DIMc; j++) v += x[j] * sW1n[j * DIMc + j2];
                yn[j2] = v;
            }
            store_row10(yout + (size_t)i * RSTRIDE, yn);
        }
    }
}

// ---------- final ----------
__global__ void k_final(float* __restrict__ out) {
    int g = blockIdx.x * blockDim.x + threadIdx.x;
    if (g < Gg) {
        float c = fmaxf(g_cnt[g], 1.0f);
        float s = g_sacc[g] / c;
        out[g] = 1.0f / (1.0f + expf(-s));
    }
}

extern "C" void kernel_launch(void* const* d_in, const int* in_sizes, int n_in,
                              void* d_out, int out_size) {
    const float* h   = (const float*)d_in[0];
    const int*   src = (const int*)d_in[1];
    const int*   dst = (const int*)d_in[2];
    const int*   ng  = (const int*)d_in[3];
    const float* W1[5]; const float* b1[5]; const float* W2[5];
    const float* b2[5]; const float* ll[5];
    for (int i = 0; i < 5; i++) {
        W1[i] = (const float*)d_in[4 + 5 * i + 0];
        b1[i] = (const float*)d_in[4 + 5 * i + 1];
        W2[i] = (const float*)d_in[4 + 5 * i + 2];
        b2[i] = (const float*)d_in[4 + 5 * i + 3];
        ll[i] = (const float*)d_in[4 + 5 * i + 4];
    }
    float* out = (float*)d_out;

    const int TB = 256;
    int nblk = (Nn + TB - 1) / TB;
    int eblk = (Ee + TB - 1) / TB;
    int gblk = (Gg + TB - 1) / TB;
    int cblk = (CSRP + TB - 1) / TB;
    // pair-per-node: 2 threads per node
    int lblk = ((Nn * 2) + TB - 1) / TB;

    k_init<<<nblk, TB>>>();
    k_fillcsr<<<cblk, TB>>>();
    k_hist<<<eblk, TB>>>(dst);
    k_scan1<<<NB_SCAN, SCAN_B>>>();
    k_scan2<<<1, SCAN_B>>>(NB_SCAN);
    k_scan3<<<NB_SCAN, SCAN_B>>>();
    k_scatter<<<eblk, TB>>>(src, dst);

    k_proj1<<<nblk, TB>>>(h, W1[0], ng);

    k_layer<0, false><<<lblk, TB>>>(b1[0], W2[0], b2[0], ll[0], W1[1], ng);
    k_layer<1, false><<<lblk, TB>>>(b1[1], W2[1], b2[1], ll[1], W1[2], ng);
    k_layer<0, false><<<lblk, TB>>>(b1[2], W2[2], b2[2], ll[2], W1[3], ng);
    k_layer<1, false><<<lblk, TB>>>(b1[3], W2[3], b2[3], ll[3], W1[4], ng);
    k_layer<0, true ><<<lblk, TB>>>(b1[4], W2[4], b2[4], ll[4], nullptr, ng);

    k_final<<<gblk, TB>>>(out);
}

// round 4
// speedup vs baseline: 1.3597x; 1.0429x over previous
#include <cuda_runtime.h>
#include <cuda_fp16.h>
#include <math.h>

#define Nn 500000
#define Ee 16000000
#define Gg 5000
#define DIMc 10
#define FINc 64
#define ALLOC_B 1024
#define NB_ALLOC ((Nn + ALLOC_B - 1) / ALLOC_B)   // 489
#define CSRP (Ee + 4000000)                        // padded CSR capacity (20M)
#define RSTRIDE 16                                 // halves per row (32 bytes)
#define PERM_PAD 128

// ---------- static device scratch ----------
// Feature tables: Nn+1 rows; row Nn is the dummy zero row (never written).
__device__ __align__(16) __half g_ha[((size_t)Nn + 1) * RSTRIDE];
__device__ __align__(16) __half g_hb[((size_t)Nn + 1) * RSTRIDE];
__device__ int   g_deg[Nn + 1];
__device__ int   g_rowptr[Nn + 1];
__device__ int   g_cursor[Nn];
__device__ int   g_csr[CSRP];
__device__ int   g_perm[Nn + PERM_PAD];
__device__ int   g_dbin[256];
__device__ int   g_dcur[256];
__device__ int   g_total;
__device__ float g_sacc[Gg];
__device__ float g_cnt[Gg];

// ---------- 1: init ----------
__global__ void k_init() {
    int i = blockIdx.x * blockDim.x + threadIdx.x;
    if (i <= Nn) g_deg[i] = 0;
    if (i < Gg) { g_sacc[i] = 0.0f; g_cnt[i] = 0.0f; }
    if (i < 256) g_dbin[i] = 0;
    if (i < PERM_PAD) g_perm[Nn + i] = Nn;
    if (i == 0) { g_total = 0; g_rowptr[Nn] = 0; }
}

// ---------- 2: degree histogram ----------
__global__ void k_hist(const int* __restrict__ dst) {
    int e = blockIdx.x * blockDim.x + threadIdx.x;
    if (e < Ee) atomicAdd(&g_deg[dst[e]], 1);
}

// ---------- 3: segment allocation (block scan + one global atomic) + degree-bin hist ----------
__global__ void k_alloc() {
    __shared__ int sh[ALLOC_B];
    __shared__ int shist[256];
    __shared__ int sbase;
    int t = threadIdx.x;
    if (t < 256) shist[t] = 0;
    int gid = blockIdx.x * ALLOC_B + t;
    int deg = (gid < Nn) ? g_deg[gid] : 0;
    int pad = (deg + 7) & ~7;
    __syncthreads();
    if (gid < Nn) atomicAdd(&shist[min(deg, 255)], 1);
    sh[t] = (gid < Nn) ? pad : 0;
    __syncthreads();
    #pragma unroll
    for (int off = 1; off < ALLOC_B; off <<= 1) {
        int v = (t >= off) ? sh[t - off] : 0;
        __syncthreads();
        sh[t] += v;
        __syncthreads();
    }
    if (t == ALLOC_B - 1) sbase = atomicAdd(&g_total, sh[ALLOC_B - 1]);
    __syncthreads();
    if (gid < Nn) {
        int r = sbase + sh[t] - ((gid < Nn) ? pad : 0);
        g_rowptr[gid] = r;
        g_cursor[gid] = r;
    }
    if (t < 256 && shist[t]) atomicAdd(&g_dbin[t], shist[t]);
}

// ---------- 4: scatter edges into CSR; block 0 additionally scans degree bins ----------
__global__ void k_scatter(const int* __restrict__ src, const int* __restrict__ dst) {
    int e = blockIdx.x * blockDim.x + threadIdx.x;
    if (e < Ee) {
        int p = atomicAdd(&g_cursor[dst[e]], 1);
        g_csr[p] = src[e];
    }
    if (blockIdx.x == 0) {
        __shared__ int s[256];
        int t = threadIdx.x;                 // blockDim == 256
        int v = g_dbin[t];
        s[t] = v;
        __syncthreads();
        #pragma unroll
        for (int off = 1; off < 256; off <<= 1) {
            int q = (t >= off) ? s[t - off] : 0;
            __syncthreads();
            s[t] += q;
            __syncthreads();
        }
        g_dcur[t] = s[t] - v;                // exclusive bucket base
    }
}

// ---------- helpers ----------
__device__ __forceinline__ void add8(float* acc, uint4 v) {
    float2 f;
    f = __half22float2(*reinterpret_cast<__half2*>(&v.x)); acc[0] += f.x; acc[1] += f.y;
    f = __half22float2(*reinterpret_cast<__half2*>(&v.y)); acc[2] += f.x; acc[3] += f.y;
    f = __half22float2(*reinterpret_cast<__half2*>(&v.z)); acc[4] += f.x; acc[5] += f.y;
    f = __half22float2(*reinterpret_cast<__half2*>(&v.w)); acc[6] += f.x; acc[7] += f.y;
}

__device__ __forceinline__ void store_row10(__half* row, const float* y) {
    __half2 p0 = __floats2half2_rn(y[0], y[1]);
    __half2 p1 = __floats2half2_rn(y[2], y[3]);
    __half2 p2 = __floats2half2_rn(y[4], y[5]);
    __half2 p3 = __floats2half2_rn(y[6], y[7]);
    __half2 p4 = __floats2half2_rn(y[8], y[9]);
    uint4 o;
    o.x = *reinterpret_cast<unsigned*>(&p0);
    o.y = *reinterpret_cast<unsigned*>(&p1);
    o.z = *reinterpret_cast<unsigned*>(&p2);
    o.w = *reinterpret_cast<unsigned*>(&p3);
    *reinterpret_cast<uint4*>(row) = o;
    *reinterpret_cast<unsigned*>(row + 8) = *reinterpret_cast<unsigned*>(&p4);
}

// ---------- 5: proj1 (coalesced, 8 lanes/node) + perm build + CSR pad fill + counts ----------
__global__ void k_proj1(const float* __restrict__ h, const float* __restrict__ W1,
                        const int* __restrict__ ng) {
    __shared__ float sW[FINc * DIMc];
    for (int t = threadIdx.x; t < FINc * DIMc; t += blockDim.x) sW[t] = W1[t];
    __syncthreads();

    int gtid = blockIdx.x * blockDim.x + threadIdx.x;   // grid sized exactly Nn*8
    int i = gtid >> 3;
    int sub8 = gtid & 7;

    const float4* hp = reinterpret_cast<const float4*>(h + (size_t)i * FINc + sub8 * 8);
    float4 a = __ldg(hp);
    float4 b = __ldg(hp + 1);

    float acc[DIMc];
    const float* w = sW + (sub8 * 8) * DIMc;
    #pragma unroll
    for (int j = 0; j < DIMc; j++) {
        float v;
        v  = a.x * w[0 * DIMc + j];
        v += a.y * w[1 * DIMc + j];
        v += a.z * w[2 * DIMc + j];
        v += a.w * w[3 * DIMc + j];
        v += b.x * w[4 * DIMc + j];
        v += b.y * w[5 * DIMc + j];
        v += b.z * w[6 * DIMc + j];
        v += b.w * w[7 * DIMc + j];
        acc[j] = v;
    }
    #pragma unroll
    for (int off = 4; off > 0; off >>= 1) {
        #pragma unroll
        for (int j = 0; j < DIMc; j++)
            acc[j] += __shfl_down_sync(0xffffffffu, acc[j], off, 8);
    }

    if (sub8 == 0) {
        store_row10(g_ha + (size_t)i * RSTRIDE, acc);
        atomicAdd(&g_cnt[ng[i]], 1.0f);
        int d = g_deg[i];
        int r = atomicAdd(&g_dcur[min(d, 255)], 1);
        g_perm[r] = i;
        int rp = g_rowptr[i];
        int pd = (d + 7) & ~7;
        for (int q = d; q < pd; q++) g_csr[rp + q] = Nn;  // dummy node
    }
}

// ---------- 6-10: fused layer over degree-sorted nodes ----------
template <int PING, bool LAST>
__global__ void __launch_bounds__(256) k_layer(
        const float* __restrict__ b1, const float* __restrict__ W2,
        const float* __restrict__ b2, const float* __restrict__ l,
        const float* __restrict__ W1n, const int* __restrict__ ng) {
    const __half* __restrict__ yin = (PING == 0) ? g_ha : g_hb;
    __half* __restrict__       yout = (PING == 0) ? g_hb : g_ha;

    __shared__ float sW2[DIMc * DIMc], sW1n[DIMc * DIMc], sb1[DIMc], sb2[DIMc], sl[DIMc];
    int t = threadIdx.x;
    if (t < DIMc * DIMc) {
        sW2[t] = W2[t];
        if (!LAST) sW1n[t] = W1n[t];
    }
    if (t < DIMc) { sb1[t] = b1[t]; sb2[t] = b2[t]; sl[t] = l[t]; }
    __syncthreads();

    int lane = t & 31;
    int warp_global = (blockIdx.x * blockDim.x + t) >> 5;
    int sub = lane & 1;
    int idx = warp_global * 16 + (lane >> 1);     // < Nn + PERM_PAD by grid sizing
    int i = g_perm[idx];                          // i == Nn for padding entries

    int e0 = g_rowptr[i];
    int deg = g_deg[i];
    int iters = (deg + 7) >> 3;
    int itersW = __reduce_max_sync(0xffffffffu, iters);

    float acc[8] = {0, 0, 0, 0, 0, 0, 0, 0};
    add8(acc, __ldg(reinterpret_cast<const uint4*>(yin + (size_t)i * RSTRIDE + sub * 8)));

    const int baselane = lane & ~1;
    for (int it = 0; it < itersW; ++it) {
        bool live = (it < iters);
        int cidx = e0 + it * 8 + sub * 4;         // in-bounds by construction (slack)
        int4 idv = *reinterpret_cast<const int4*>(g_csr + cidx);
        int id[4] = {idv.x, idv.y, idv.z, idv.w};
        #pragma unroll
        for (int k = 0; k < 8; ++k) {
            int s = __shfl_sync(0xffffffffu, id[k & 3], baselane + (k >> 2));
            if (!live) s = Nn;                    // dummy zero row
            add8(acc, __ldg(reinterpret_cast<const uint4*>(
                    yin + (size_t)s * RSTRIDE + sub * 8)));
        }
    }

    float v8 = __shfl_down_sync(0xffffffffu, acc[0], 1);
    float v9 = __shfl_down_sync(0xffffffffu, acc[1], 1);

    if (sub == 0 && i < Nn) {
        float u[DIMc];
        #pragma unroll
        for (int j = 0; j < 8; j++) u[j] = fmaxf(acc[j] + sb1[j], 0.0f);
        u[8] = fmaxf(v8 + sb1[8], 0.0f);
        u[9] = fmaxf(v9 + sb1[9], 0.0f);

        float x[DIMc];
        #pragma unroll
        for (int j = 0; j < DIMc; j++) {
            float tv = sb2[j];
            #pragma unroll
            for (int k = 0; k < DIMc; k++) tv += u[k] * sW2[k * DIMc + j];
            x[j] = fmaxf(tv, 0.0f);
        }

        float dot = 0.0f;
        #pragma unroll
        for (int j = 0; j < DIMc; j++) dot += x[j] * sl[j];
        atomicAdd(&g_sacc[ng[i]], dot);

        if (!LAST) {
            float yn[DIMc];
            #pragma unroll
            for (int j2 = 0; j2 < DIMc; j2++) {
                float v = 0.0f;
                #pragma unroll
                for (int j = 0; j < DIMc; j++) v += x[j] * sW1n[j * DIMc + j2];
                yn[j2] = v;
            }
            store_row10(yout + (size_t)i * RSTRIDE, yn);
        }
    }
}

// ---------- 11: final ----------
__global__ void k_final(float* __restrict__ out) {
    int g = blockIdx.x * blockDim.x + threadIdx.x;
    if (g < Gg) {
        float c = fmaxf(g_cnt[g], 1.0f);
        float s = g_sacc[g] / c;
        out[g] = 1.0f / (1.0f + expf(-s));
    }
}

extern "C" void kernel_launch(void* const* d_in, const int* in_sizes, int n_in,
                              void* d_out, int out_size) {
    const float* h   = (const float*)d_in[0];
    const int*   src = (const int*)d_in[1];
    const int*   dst = (const int*)d_in[2];
    const int*   ng  = (const int*)d_in[3];
    const float* W1[5]; const float* b1[5]; const float* W2[5];
    const float* b2[5]; const float* ll[5];
    for (int i = 0; i < 5; i++) {
        W1[i] = (const float*)d_in[4 + 5 * i + 0];
        b1[i] = (const float*)d_in[4 + 5 * i + 1];
        W2[i] = (const float*)d_in[4 + 5 * i + 2];
        b2[i] = (const float*)d_in[4 + 5 * i + 3];
        ll[i] = (const float*)d_in[4 + 5 * i + 4];
    }
    float* out = (float*)d_out;

    const int TB = 256;
    int nblk = (Nn + TB) / TB;                 // covers Nn inclusive index
    int eblk = (Ee + TB - 1) / TB;
    int gblk = (Gg + TB - 1) / TB;
    int pblk = (Nn * 8) / TB;                  // exact: 15625
    int lblk = (Nn * 2 + TB - 1) / TB;         // pair-per-node

    k_init<<<nblk, TB>>>();                                            // 1
    k_hist<<<eblk, TB>>>(dst);                                         // 2
    k_alloc<<<NB_ALLOC, ALLOC_B>>>();                                  // 3
    k_scatter<<<eblk, TB>>>(src, dst);                                 // 4
    k_proj1<<<pblk, TB>>>(h, W1[0], ng);                               // 5
    k_layer<0, false><<<lblk, TB>>>(b1[0], W2[0], b2[0], ll[0], W1[1], ng);  // 6 (profiled)
    k_layer<1, false><<<lblk, TB>>>(b1[1], W2[1], b2[1], ll[1], W1[2], ng);
    k_layer<0, false><<<lblk, TB>>>(b1[2], W2[2], b2[2], ll[2], W1[3], ng);
    k_layer<1, false><<<lblk, TB>>>(b1[3], W2[3], b2[3], ll[3], W1[4], ng);
    k_layer<0, true ><<<lblk, TB>>>(b1[4], W2[4], b2[4], ll[4], nullptr, ng);
    k_final<<<gblk, TB>>>(out);
}